// round 9
// baseline (speedup 1.0000x reference)
#include <cuda_runtime.h>

typedef unsigned long long ull;

#define HID   128
#define TT    512
#define NB    2048
#define RPC   8
#define NCTA  (NB / RPC)   // 256
#define NTHR  256

// Blocked weights: [kq][gate*128+j][k%4] -> 16B load at (kq,g,j) = W[g,j][4 consecutive k]
// 0: Wh0, 1: Wi1, 2: Wh1
__device__ __align__(16) float g_wt[3][128 * 384];

__global__ void transpose_k(const float* __restrict__ Wh0,
                            const float* __restrict__ Wi1,
                            const float* __restrict__ Wh1) {
    int idx = blockIdx.x * blockDim.x + threadIdx.x;
    if (idx >= 128 * 384) return;
    int kq  = idx / 1536;
    int rem = idx - kq * 1536;
    int gj  = rem >> 2;
    int k   = kq * 4 + (rem & 3);
    g_wt[0][idx] = Wh0[gj * HID + k];
    g_wt[1][idx] = Wi1[gj * HID + k];
    g_wt[2][idx] = Wh1[gj * HID + k];
}

// ---- packed f32x2 helpers ----
__device__ __forceinline__ void ffma2(ull& d, ull a, ull b) {
    asm("fma.rn.f32x2 %0, %1, %2, %0;" : "+l"(d) : "l"(a), "l"(b));
}
__device__ __forceinline__ float hadd2(ull v) {
    float lo, hi; asm("mov.b64 {%0, %1}, %2;" : "=f"(lo), "=f"(hi) : "l"(v)); return lo + hi;
}
__device__ __forceinline__ float tanhap(float x) {
    float y; asm("tanh.approx.f32 %0, %1;" : "=f"(y) : "f"(x)); return y;
}
__device__ __forceinline__ float sigap(float x) {
    return fmaf(tanhap(0.5f * x), 0.5f, 0.5f);
}

__global__ void __launch_bounds__(NTHR, 2)
gru_kernel(const float* __restrict__ x,
           const float* __restrict__ noise_z,
           const float* __restrict__ context,
           const float* __restrict__ Wi0,
           const float* __restrict__ bi0,
           const float* __restrict__ bh0,
           const float* __restrict__ bi1,
           const float* __restrict__ bh1,
           const float* __restrict__ Wa,
           const float* __restrict__ ba,
           float* __restrict__ out) {
    __shared__ __align__(16) float h0s[RPC][128];     // [r][k], in-place update
    __shared__ __align__(16) float h1s[RPC][128];
    __shared__ __align__(16) float red[3][RPC][128];  // partial-gate exchange
    __shared__ __align__(16) float was[256];          // Wa staged
    __shared__ __align__(16) float decs[2][RPC];      // feedback [s][r]

    const int tid = threadIdx.x;
    const int grp = tid >> 7;          // 0: L0 r,z + Ui side ; 1: L0 n + Vh side + head
    const int j   = tid & 127;
    const int er0 = grp * 4;           // epilogue-owned rows er0..er0+3
    const int brow0 = blockIdx.x * RPC;

    // ---- init ----
    for (int i = tid; i < RPC * 128; i += NTHR) {
        (&h0s[0][0])[i] = 0.f;
        (&h1s[0][0])[i] = 0.f;
    }
    was[tid] = Wa[tid];
    if (tid < 2 * RPC) {
        int r = tid >> 1, s = tid & 1;
        decs[s][r] = noise_z[(brow0 + r) * 2 + s];
    }

    // per-thread constants (biases, dec weights)
    const float bh0r = bh0[j], bh0z = bh0[128 + j], bh0n = bh0[256 + j];
    const float brzr = bi1[j] + bh1[j];
    const float brzz = bi1[128 + j] + bh1[128 + j];
    const float binn = bi1[256 + j];
    const float bhnn = bh1[256 + j];
    float wd0[3], wd1[3];
#pragma unroll
    for (int g = 0; g < 3; ++g) {
        wd0[g] = Wi0[(g * 128 + j) * 12 + 0];
        wd1[g] = Wi0[(g * 128 + j) * 12 + 1];
    }

    // ctx gates (bi0 + context part) for the 4 owned rows, in registers
    float cg[3][4];
#pragma unroll
    for (int g = 0; g < 3; ++g) {
        int gj = g * 128 + j;
        float wrow[10];
#pragma unroll
        for (int e = 0; e < 10; ++e) wrow[e] = Wi0[gj * 12 + 2 + e];
        float b = bi0[gj];
        for (int q = 0; q < 4; ++q) {
            float acc = b;
#pragma unroll
            for (int e = 0; e < 10; ++e) acc += context[(brow0 + er0 + q) * 10 + e] * wrow[e];
            cg[g][q] = acc;
        }
    }

    // head role (group B): j -> (row hr, state hs, k-slice hl)
    const int hr = j >> 4;
    const int hs = (j >> 3) & 1;
    const int hl = j & 7;
    const float bas = ba[hs];

    const ulonglong2* wb0 = reinterpret_cast<const ulonglong2*>(g_wt[0]) + j;  // Wh0
    const ulonglong2* wbu = reinterpret_cast<const ulonglong2*>(g_wt[1]) + j;  // Wi1
    const ulonglong2* wbv = reinterpret_cast<const ulonglong2*>(g_wt[2]) + j;  // Wh1

    __syncthreads();

    for (int t = -1; t < TT; ++t) {
        // ===== layer 0 GEMM (gate split: A -> r,z ; B -> n) =====
        float f0[8], f1[8];
        if (grp == 0) {
            ull Ar[8], Az[8];
#pragma unroll
            for (int rr = 0; rr < 8; ++rr) { Ar[rr] = 0ull; Az[rr] = 0ull; }
#pragma unroll 2
            for (int kq = 0; kq < 32; ++kq) {
                ulonglong2 wr = wb0[kq * 384];
                ulonglong2 wz = wb0[kq * 384 + 128];
#pragma unroll
                for (int rr = 0; rr < 8; ++rr) {
                    ulonglong2 h = *reinterpret_cast<const ulonglong2*>(&h0s[rr][kq * 4]);
                    ffma2(Ar[rr], wr.x, h.x); ffma2(Ar[rr], wr.y, h.y);
                    ffma2(Az[rr], wz.x, h.x); ffma2(Az[rr], wz.y, h.y);
                }
            }
#pragma unroll
            for (int rr = 0; rr < 8; ++rr) { f0[rr] = hadd2(Ar[rr]); f1[rr] = hadd2(Az[rr]); }
#pragma unroll
            for (int q = 0; q < 4; ++q) {
                red[0][4 + q][j] = f0[4 + q];
                red[1][4 + q][j] = f1[4 + q];
            }
        } else {
            ull An[8];
#pragma unroll
            for (int rr = 0; rr < 8; ++rr) An[rr] = 0ull;
#pragma unroll 2
            for (int kq = 0; kq < 32; ++kq) {
                ulonglong2 wn = wb0[kq * 384 + 256];
#pragma unroll
                for (int rr = 0; rr < 8; ++rr) {
                    ulonglong2 h = *reinterpret_cast<const ulonglong2*>(&h0s[rr][kq * 4]);
                    ffma2(An[rr], wn.x, h.x); ffma2(An[rr], wn.y, h.y);
                }
            }
#pragma unroll
            for (int rr = 0; rr < 8; ++rr) f0[rr] = hadd2(An[rr]);
#pragma unroll
            for (int q = 0; q < 4; ++q) red[2][q][j] = f0[q];
        }
        __syncthreads();   // BAR1: L0 partials visible (and prev-step decs ordered)

        // layer-0 epilogue: 4 owned rows, in-place h0 update
#pragma unroll
        for (int q = 0; q < 4; ++q) {
            int r = er0 + q;
            float rsum = grp ? red[0][r][j] : f0[q];
            float zsum = grp ? red[1][r][j] : f1[q];
            float ghn  = grp ? f0[4 + q]    : red[2][r][j];
            float d0 = decs[0][r], d1 = decs[1][r];
            float rg = sigap(cg[0][q] + d0 * wd0[0] + d1 * wd1[0] + rsum + bh0r);
            float zg = sigap(cg[1][q] + d0 * wd0[1] + d1 * wd1[1] + zsum + bh0z);
            float ng = tanhap(cg[2][q] + d0 * wd0[2] + d1 * wd1[2] + rg * (ghn + bh0n));
            float ho = h0s[r][j];
            h0s[r][j] = ng + zg * (ho - ng);
        }
        __syncthreads();   // BAR2: new h0 visible

        // ===== layer 1 GEMM (side split: A -> Ui@h0 ; B -> Vh@h1), uniform code =====
        float s0[8], s1[8], s2[8];
        {
            const ulonglong2* wp = grp ? wbv : wbu;
            const float (*hp)[128] = grp ? h1s : h0s;
            ull G0[8], G1[8], G2[8];
#pragma unroll
            for (int rr = 0; rr < 8; ++rr) { G0[rr] = 0ull; G1[rr] = 0ull; G2[rr] = 0ull; }
#pragma unroll 2
            for (int kq = 0; kq < 32; ++kq) {
                ulonglong2 w0 = wp[kq * 384];
                ulonglong2 w1 = wp[kq * 384 + 128];
                ulonglong2 w2 = wp[kq * 384 + 256];
#pragma unroll
                for (int rr = 0; rr < 8; ++rr) {
                    ulonglong2 h = *reinterpret_cast<const ulonglong2*>(&hp[rr][kq * 4]);
                    ffma2(G0[rr], w0.x, h.x); ffma2(G0[rr], w0.y, h.y);
                    ffma2(G1[rr], w1.x, h.x); ffma2(G1[rr], w1.y, h.y);
                    ffma2(G2[rr], w2.x, h.x); ffma2(G2[rr], w2.y, h.y);
                }
            }
#pragma unroll
            for (int rr = 0; rr < 8; ++rr) {
                s0[rr] = hadd2(G0[rr]); s1[rr] = hadd2(G1[rr]); s2[rr] = hadd2(G2[rr]);
            }
        }
        // each group exports the partner's epilogue rows
        {
            int wb = (grp ^ 1) * 4;
#pragma unroll
            for (int q = 0; q < 4; ++q) {
                red[0][wb + q][j] = s0[wb + q];
                red[1][wb + q][j] = s1[wb + q];
                red[2][wb + q][j] = s2[wb + q];
            }
        }
        __syncthreads();   // BAR3: L1 partials visible

        // layer-1 epilogue: 4 owned rows, in-place h1 update
#pragma unroll
        for (int q = 0; q < 4; ++q) {
            int r = er0 + q;
            float uir = grp ? red[0][r][j] : s0[q + er0];
            float uiz = grp ? red[1][r][j] : s1[q + er0];
            float uin = grp ? red[2][r][j] : s2[q + er0];
            float vhr = grp ? s0[q + er0] : red[0][r][j];
            float vhz = grp ? s1[q + er0] : red[1][r][j];
            float vhn = grp ? s2[q + er0] : red[2][r][j];
            float rg = sigap(uir + vhr + brzr);
            float zg = sigap(uiz + vhz + brzz);
            float ng = tanhap(uin + binn + rg * (vhn + bhnn));
            float ho = h1s[r][j];
            h1s[r][j] = ng + zg * (ho - ng);
        }
        __syncthreads();   // BAR4: new h1 visible

        // ===== output head (group B) + autoregressive feedback =====
        if (t >= 0) {
            if (grp == 1) {
                ull acc = 0ull;
                const float* hrow = &h1s[hr][hl * 16];
                const float* wrow = &was[hs * 128 + hl * 16];
#pragma unroll
                for (int qq = 0; qq < 4; ++qq) {
                    ulonglong2 hv = *reinterpret_cast<const ulonglong2*>(&hrow[qq * 4]);
                    ulonglong2 wv = *reinterpret_cast<const ulonglong2*>(&wrow[qq * 4]);
                    ffma2(acc, wv.x, hv.x);
                    ffma2(acc, wv.y, hv.y);
                }
                float v = hadd2(acc);
                v += __shfl_xor_sync(0xffffffffu, v, 1, 8);
                v += __shfl_xor_sync(0xffffffffu, v, 2, 8);
                v += __shfl_xor_sync(0xffffffffu, v, 4, 8);
                if (hl == 0) {
                    float o = v + bas;
                    decs[hs][hr] = o;
                    out[(size_t)(brow0 + hr) * (TT * 2) + t * 2 + hs] = o;
                }
            }
        } else {
            if (tid < 2 * RPC) {
                int r = tid >> 1, s = tid & 1;
                decs[s][r] = x[(size_t)(brow0 + r) * (TT * 2) + s];
            }
        }
        // decs ordering for next step handled by next iteration's BAR1
    }
}

extern "C" void kernel_launch(void* const* d_in, const int* in_sizes, int n_in,
                              void* d_out, int out_size) {
    const float* x       = (const float*)d_in[0];
    const float* noise_z = (const float*)d_in[1];
    const float* context = (const float*)d_in[2];
    const float* Wi0     = (const float*)d_in[3];
    const float* Wh0     = (const float*)d_in[4];
    const float* bi0     = (const float*)d_in[5];
    const float* bh0     = (const float*)d_in[6];
    const float* Wi1     = (const float*)d_in[7];
    const float* Wh1     = (const float*)d_in[8];
    const float* bi1     = (const float*)d_in[9];
    const float* bh1     = (const float*)d_in[10];
    const float* Wa      = (const float*)d_in[11];
    const float* ba      = (const float*)d_in[12];
    float* out = (float*)d_out;

    transpose_k<<<192, 256>>>(Wh0, Wi1, Wh1);
    gru_kernel<<<NCTA, NTHR>>>(x, noise_z, context, Wi0, bi0, bh0,
                               bi1, bh1, Wa, ba, out);
}

// round 10
// speedup vs baseline: 1.0713x; 1.0713x over previous
#include <cuda_runtime.h>

typedef unsigned long long ull;

#define HID   128
#define TT    512
#define NB    2048
#define NCTA  296          // 2 per SM on 148 SMs; 272 CTAs x 7 rows + 24 x 6 rows
#define NTHR  256

// Blocked weights: [kq][gate*128+j][k%4] -> 16B load at (kq,g,j) = W[g,j][4 consecutive k]
// 0: Wh0, 1: Wi1, 2: Wh1
__device__ __align__(16) float g_wt[3][128 * 384];

__global__ void transpose_k(const float* __restrict__ Wh0,
                            const float* __restrict__ Wi1,
                            const float* __restrict__ Wh1) {
    int idx = blockIdx.x * blockDim.x + threadIdx.x;
    if (idx >= 128 * 384) return;
    int kq  = idx / 1536;
    int rem = idx - kq * 1536;
    int gj  = rem >> 2;
    int k   = kq * 4 + (rem & 3);
    g_wt[0][idx] = Wh0[gj * HID + k];
    g_wt[1][idx] = Wi1[gj * HID + k];
    g_wt[2][idx] = Wh1[gj * HID + k];
}

// ---- packed f32x2 helpers ----
__device__ __forceinline__ void ffma2(ull& d, ull a, ull b) {
    asm("fma.rn.f32x2 %0, %1, %2, %0;" : "+l"(d) : "l"(a), "l"(b));
}
__device__ __forceinline__ float hadd2(ull v) {
    float lo, hi; asm("mov.b64 {%0, %1}, %2;" : "=f"(lo), "=f"(hi) : "l"(v)); return lo + hi;
}
__device__ __forceinline__ float tanhap(float x) {
    float y; asm("tanh.approx.f32 %0, %1;" : "=f"(y) : "f"(x)); return y;
}
__device__ __forceinline__ float sigap(float x) {
    return fmaf(tanhap(0.5f * x), 0.5f, 0.5f);
}

__global__ void __launch_bounds__(NTHR, 2)
gru_kernel(const float* __restrict__ x,
           const float* __restrict__ noise_z,
           const float* __restrict__ context,
           const float* __restrict__ Wi0,
           const float* __restrict__ bi0,
           const float* __restrict__ bh0,
           const float* __restrict__ bi1,
           const float* __restrict__ bh1,
           const float* __restrict__ Wa,
           const float* __restrict__ ba,
           float* __restrict__ out) {
    __shared__ __align__(16) float h0s[2][8][128];   // [buf][r][k]
    __shared__ __align__(16) float h1s[2][8][128];
    __shared__ __align__(16) float ctxgi[3][8][128]; // [g][r][j]
    __shared__ __align__(16) float was[256];         // Wa staged
    __shared__ __align__(16) float decs[2][8];       // feedback [s][r]

    const int tid = threadIdx.x;
    const int hf  = tid >> 7;          // row-half
    const int j   = tid & 127;         // output neuron

    // variable rows per CTA: first 272 CTAs get 7 rows, last 24 get 6
    const int bid = blockIdx.x;
    const int brow0 = (bid < 272) ? bid * 7 : 1904 + (bid - 272) * 6;
    const int nrows = (bid < 272) ? 7 : 6;
    const int half0 = (nrows + 1) >> 1;          // rows in half 0
    const int r0  = hf ? half0 : 0;              // first row this thread epilogues
    const int myr = hf ? (nrows - half0) : half0;// rows this thread epilogues (3 or 4)

    // ---- init ----
    for (int i = tid; i < 2 * 8 * 128; i += NTHR) {
        (&h0s[0][0][0])[i] = 0.f;
        (&h1s[0][0][0])[i] = 0.f;
    }
    was[tid] = Wa[tid];
    if (tid < 16) {
        int r = tid >> 1, s = tid & 1;
        if (r < nrows) decs[s][r] = noise_z[(brow0 + r) * 2 + s];
    }

    // per-thread constants
    const float bh0r = bh0[j], bh0z = bh0[128 + j], bh0n = bh0[256 + j];
    const float brzr = bi1[j] + bh1[j];
    const float brzz = bi1[128 + j] + bh1[128 + j];
    const float binn = bi1[256 + j];
    const float bhnn = bh1[256 + j];
    float wd0[3], wd1[3];
#pragma unroll
    for (int g = 0; g < 3; ++g) {
        wd0[g] = Wi0[(g * 128 + j) * 12 + 0];
        wd1[g] = Wi0[(g * 128 + j) * 12 + 1];
    }

    // ctx gates: bi0 + context-part (time invariant), for owned live rows
#pragma unroll
    for (int g = 0; g < 3; ++g) {
        int gj = g * 128 + j;
        float wrow[10];
#pragma unroll
        for (int e = 0; e < 10; ++e) wrow[e] = Wi0[gj * 12 + 2 + e];
        float b = bi0[gj];
        for (int q = 0; q < 4; ++q) {
            int r = r0 + q;
            if (q < myr) {
                float acc = b;
#pragma unroll
                for (int e = 0; e < 10; ++e) acc += context[(brow0 + r) * 10 + e] * wrow[e];
                ctxgi[g][r][j] = acc;
            }
        }
    }

    // head role (threads 0..127): (row hr, state hs, k-slice hl)
    const int hr = (tid >> 4) & 7;
    const int hs = (tid >> 3) & 1;
    const int hl = tid & 7;
    const float bas = ba[hs];

    const ulonglong2* w0b = reinterpret_cast<const ulonglong2*>(g_wt[0]) + j;
    const ulonglong2* wib = reinterpret_cast<const ulonglong2*>(g_wt[1]) + j;
    const ulonglong2* whb = reinterpret_cast<const ulonglong2*>(g_wt[2]) + j;

    __syncthreads();

    int p = 0;
    for (int t = -1; t < TT; ++t) {
        // ================= layer 0: gh0 = h0_old @ Wh0^T =================
        ull A0[4], A1[4], A2[4];
#pragma unroll
        for (int rr = 0; rr < 4; ++rr) { A0[rr] = 0ull; A1[rr] = 0ull; A2[rr] = 0ull; }
        {
            const float (*hb)[128] = h0s[p];
#pragma unroll 2
            for (int kq = 0; kq < 32; ++kq) {
                ulonglong2 wA = w0b[kq * 384];
                ulonglong2 wB = w0b[kq * 384 + 128];
                ulonglong2 wC = w0b[kq * 384 + 256];
#pragma unroll
                for (int rr = 0; rr < 4; ++rr) {
                    ulonglong2 h = *reinterpret_cast<const ulonglong2*>(&hb[r0 + rr][kq * 4]);
                    ffma2(A0[rr], wA.x, h.x); ffma2(A0[rr], wA.y, h.y);
                    ffma2(A1[rr], wB.x, h.x); ffma2(A1[rr], wB.y, h.y);
                    ffma2(A2[rr], wC.x, h.x); ffma2(A2[rr], wC.y, h.y);
                }
            }
        }

        // layer-0 epilogue: owned live rows
#pragma unroll
        for (int rr = 0; rr < 4; ++rr) {
            if (rr < myr) {
                int r = r0 + rr;
                float d0 = decs[0][r], d1 = decs[1][r];
                float rg = sigap(ctxgi[0][r][j] + d0 * wd0[0] + d1 * wd1[0] + hadd2(A0[rr]) + bh0r);
                float zg = sigap(ctxgi[1][r][j] + d0 * wd0[1] + d1 * wd1[1] + hadd2(A1[rr]) + bh0z);
                float ng = tanhap(ctxgi[2][r][j] + d0 * wd0[2] + d1 * wd1[2] +
                                  rg * (hadd2(A2[rr]) + bh0n));
                float ho = h0s[p][r][j];
                h0s[p ^ 1][r][j] = ng + zg * (ho - ng);
            }
        }
        __syncthreads();   // BAR1: new h0 visible

        // ====== layer 1: gi1 (r/z fused with gh1); n split ======
        ull Z0[4], Z1[4], Ni[4], Nh[4];
#pragma unroll
        for (int rr = 0; rr < 4; ++rr) { Z0[rr] = 0ull; Z1[rr] = 0ull; Ni[rr] = 0ull; Nh[rr] = 0ull; }
        {
            const float (*ha)[128] = h0s[p ^ 1];
            const float (*hb)[128] = h1s[p];
#pragma unroll 2
            for (int kq = 0; kq < 32; ++kq) {
                ulonglong2 U0 = wib[kq * 384];
                ulonglong2 U1 = wib[kq * 384 + 128];
                ulonglong2 U2 = wib[kq * 384 + 256];
                ulonglong2 V0 = whb[kq * 384];
                ulonglong2 V1 = whb[kq * 384 + 128];
                ulonglong2 V2 = whb[kq * 384 + 256];
#pragma unroll
                for (int rr = 0; rr < 4; ++rr) {
                    ulonglong2 a = *reinterpret_cast<const ulonglong2*>(&ha[r0 + rr][kq * 4]);
                    ulonglong2 b = *reinterpret_cast<const ulonglong2*>(&hb[r0 + rr][kq * 4]);
                    ffma2(Z0[rr], U0.x, a.x); ffma2(Z0[rr], U0.y, a.y);
                    ffma2(Z0[rr], V0.x, b.x); ffma2(Z0[rr], V0.y, b.y);
                    ffma2(Z1[rr], U1.x, a.x); ffma2(Z1[rr], U1.y, a.y);
                    ffma2(Z1[rr], V1.x, b.x); ffma2(Z1[rr], V1.y, b.y);
                    ffma2(Ni[rr], U2.x, a.x); ffma2(Ni[rr], U2.y, a.y);
                    ffma2(Nh[rr], V2.x, b.x); ffma2(Nh[rr], V2.y, b.y);
                }
            }
        }

        // layer-1 epilogue: owned live rows
#pragma unroll
        for (int rr = 0; rr < 4; ++rr) {
            if (rr < myr) {
                int r = r0 + rr;
                float rg = sigap(hadd2(Z0[rr]) + brzr);
                float zg = sigap(hadd2(Z1[rr]) + brzz);
                float ng = tanhap(hadd2(Ni[rr]) + binn + rg * (hadd2(Nh[rr]) + bhnn));
                float ho = h1s[p][r][j];
                h1s[p ^ 1][r][j] = ng + zg * (ho - ng);
            }
        }
        __syncthreads();   // BAR2: new h1 visible

        // ========== output head (threads 0..127) + autoregressive feedback ==========
        if (t >= 0) {
            if (tid < 128) {
                ull acc = 0ull;
                const float* hrow = &h1s[p ^ 1][hr][hl * 16];
                const float* wrow = &was[hs * 128 + hl * 16];
#pragma unroll
                for (int qq = 0; qq < 4; ++qq) {
                    ulonglong2 hv = *reinterpret_cast<const ulonglong2*>(&hrow[qq * 4]);
                    ulonglong2 wv = *reinterpret_cast<const ulonglong2*>(&wrow[qq * 4]);
                    ffma2(acc, wv.x, hv.x);
                    ffma2(acc, wv.y, hv.y);
                }
                float v = hadd2(acc);
                v += __shfl_xor_sync(0xffffffffu, v, 1, 8);
                v += __shfl_xor_sync(0xffffffffu, v, 2, 8);
                v += __shfl_xor_sync(0xffffffffu, v, 4, 8);
                if (hl == 0 && hr < nrows) {
                    float o = v + bas;
                    decs[hs][hr] = o;
                    out[(size_t)(brow0 + hr) * (TT * 2) + t * 2 + hs] = o;
                }
            }
        } else {
            if (tid < 16) {
                int r = tid >> 1, s = tid & 1;
                if (r < nrows) decs[s][r] = x[(size_t)(brow0 + r) * (TT * 2) + s];
            }
        }
        // no barrier here: next iteration's BAR1 orders decs (head warps must
        // arrive there after writing decs) and all h-buffer pairs are disjoint.
        p ^= 1;
    }
}

extern "C" void kernel_launch(void* const* d_in, const int* in_sizes, int n_in,
                              void* d_out, int out_size) {
    const float* x       = (const float*)d_in[0];
    const float* noise_z = (const float*)d_in[1];
    const float* context = (const float*)d_in[2];
    const float* Wi0     = (const float*)d_in[3];
    const float* Wh0     = (const float*)d_in[4];
    const float* bi0     = (const float*)d_in[5];
    const float* bh0     = (const float*)d_in[6];
    const float* Wi1     = (const float*)d_in[7];
    const float* Wh1     = (const float*)d_in[8];
    const float* bi1     = (const float*)d_in[9];
    const float* bh1     = (const float*)d_in[10];
    const float* Wa      = (const float*)d_in[11];
    const float* ba      = (const float*)d_in[12];
    float* out = (float*)d_out;

    transpose_k<<<192, 256>>>(Wh0, Wi1, Wh1);
    gru_kernel<<<NCTA, NTHR>>>(x, noise_z, context, Wi0, bi0, bh0,
                               bi1, bh1, Wa, ba, out);
}